// round 7
// baseline (speedup 1.0000x reference)
#include <cuda_runtime.h>

// SConv2d majority-gate conv, s-domain math.
// R5: packed f32x2 — 2 horizontally-adjacent pixels per thread.
//     Leaves/nodes use fma.rn.f32x2 / mul.rn.f32x2 / add.rn.f32x2 (FFMA2 path).
//     Weights pre-packed {w/2,w/2} in smem; x pairs built from LDS.64 + packs.

#define C_IN 27
#define NOC 27
#define HH 32
#define WW 32
#define TILE_H 8
#define SM_ROWS (TILE_H + 2)       // 10
#define SM_W 36                    // [pad, haloL, 32 interior, haloR, pad]
#define SM_CH (SM_ROWS * SM_W)     // 360
#define OCG 3
#define WP2 10                     // packed-weight stride per (oc,c): 9 -> 10
#define NPAIR 128                  // pixel pairs per tile (8 rows x 16 pairs)
#define NTHR (NPAIR * 3)           // 384

typedef unsigned long long u64;

__device__ __forceinline__ u64 pk2(float lo, float hi) {
    u64 r; asm("mov.b64 %0,{%1,%2};" : "=l"(r) : "f"(lo), "f"(hi)); return r;
}
__device__ __forceinline__ void upk2(u64 v, float& lo, float& hi) {
    asm("mov.b64 {%0,%1},%2;" : "=f"(lo), "=f"(hi) : "l"(v));
}
__device__ __forceinline__ u64 ffma2(u64 a, u64 b, u64 c) {
    u64 d; asm("fma.rn.f32x2 %0,%1,%2,%3;" : "=l"(d) : "l"(a), "l"(b), "l"(c)); return d;
}
__device__ __forceinline__ u64 fmul2(u64 a, u64 b) {
    u64 d; asm("mul.rn.f32x2 %0,%1,%2;" : "=l"(d) : "l"(a), "l"(b)); return d;
}
__device__ __forceinline__ u64 fadd2(u64 a, u64 b) {
    u64 d; asm("add.rn.f32x2 %0,%1,%2;" : "=l"(d) : "l"(a), "l"(b)); return d;
}
__device__ __forceinline__ u64 maj3s2(u64 a, u64 b, u64 c, u64 NEG2) {
    u64 p = fmul2(a, b);
    u64 t = fadd2(a, b);
    u64 q = ffma2(NEG2, p, t);     // a+b-2ab
    return ffma2(q, c, p);         // ab + (a+b-2ab)c
}

__global__ __launch_bounds__(NTHR, 2) void sconv_kernel(const float* __restrict__ x,
                                                        const float* __restrict__ w,
                                                        float* __restrict__ out) {
    __shared__ __align__(16) float xs[C_IN * SM_CH];        // 38880 B (aliased later)
    __shared__ __align__(16) u64 wsm[OCG * C_IN * WP2];     // 6480 B

    int b = blockIdx.x;
    int ocg  = b % (NOC / OCG);        // 0..8
    int tile = (b / (NOC / OCG)) & 3;  // 0..3
    int n    = b / (4 * (NOC / OCG));  // 0..7
    int h0 = tile * TILE_H;
    int oc0 = ocg * OCG;

    int tid = threadIdx.x;

    // ---- stage weights packed {w/2, w/2}
    for (int idx = tid; idx < OCG * C_IN * 9; idx += NTHR) {
        int ocl = idx / (C_IN * 9);
        int rem = idx - ocl * (C_IN * 9);
        int c = rem / 9;
        int k = rem - c * 9;
        float v = 0.5f * w[(oc0 + ocl) * (C_IN * 9) + rem];
        wsm[(ocl * C_IN + c) * WP2 + k] = pk2(v, v);
    }

    // ---- stage x tile interior (coalesced); halos = -1
    const float* xn = x + (size_t)n * C_IN * HH * WW;
    for (int idx = tid; idx < C_IN * SM_ROWS * 32; idx += NTHR) {
        int rowid = idx >> 5;
        int col   = idx & 31;
        int c = rowid / SM_ROWS;
        int r = rowid - c * SM_ROWS;
        int gh = h0 + r - 1;
        float v = -1.0f;
        if ((unsigned)gh < HH)
            v = xn[(c << 10) + (gh << 5) + col];
        xs[c * SM_CH + r * SM_W + col + 2] = v;
    }
    for (int idx = tid; idx < C_IN * SM_ROWS; idx += NTHR) {
        xs[idx * SM_W + 1] = -1.0f;        // left halo (col -1)
        xs[idx * SM_W + 34] = -1.0f;       // right halo (col 32)
    }
    __syncthreads();

    int pp  = tid & (NPAIR - 1);       // pair index 0..127
    int cg  = tid >> 7;                // channel group 0..2
    int wc2 = pp & 15;                 // pair column (cols 2*wc2, 2*wc2+1)
    int hl  = pp >> 4;                 // local row 0..7

    const u64 HALF2 = pk2(0.5f, 0.5f);
    const u64 NEG2  = pk2(-2.0f, -2.0f);

    const float* xb = &xs[hl * SM_W + 2 + 2 * wc2];
    int c0 = 9 * cg;

    u64 vb[OCG][3], ub[OCG][3];

    #pragma unroll
    for (int cl = 0; cl < 9; cl++) {
        int c = c0 + cl;
        // build 9 packed x pairs for this channel (covers both pixels)
        u64 xp[9];
        #pragma unroll
        for (int kh = 0; kh < 3; kh++) {
            const float* rp = xb + c * SM_CH + kh * SM_W;
            float2 a  = *(const float2*)rp;        // x[2w], x[2w+1]
            float  bl = rp[-1];                    // x[2w-1]
            float2 cr = *(const float2*)(rp + 2);  // x[2w+2], x[2w+3]
            xp[kh * 3 + 0] = pk2(bl, a.x);
            xp[kh * 3 + 1] = pk2(a.x, a.y);
            xp[kh * 3 + 2] = pk2(a.y, cr.x);
        }
        #pragma unroll
        for (int o = 0; o < OCG; o++) {
            const u64* wb_ = &wsm[(o * C_IN + c) * WP2];
            ulonglong2 q0 = ((const ulonglong2*)wb_)[0];
            ulonglong2 q1 = ((const ulonglong2*)wb_)[1];
            ulonglong2 q2 = ((const ulonglong2*)wb_)[2];
            ulonglong2 q3 = ((const ulonglong2*)wb_)[3];
            u64 w8 = wb_[8];
            u64 wk[9] = {q0.x, q0.y, q1.x, q1.y, q2.x, q2.y, q3.x, q3.y, w8};
            u64 rkh[3];
            #pragma unroll
            for (int kh = 0; kh < 3; kh++) {
                u64 s0 = ffma2(xp[kh * 3 + 0], wk[kh * 3 + 0], HALF2);
                u64 s1 = ffma2(xp[kh * 3 + 1], wk[kh * 3 + 1], HALF2);
                u64 s2 = ffma2(xp[kh * 3 + 2], wk[kh * 3 + 2], HALF2);
                rkh[kh] = maj3s2(s0, s1, s2, NEG2);
            }
            vb[o][cl % 3] = maj3s2(rkh[0], rkh[1], rkh[2], NEG2);
        }
        if (cl % 3 == 2) {
            #pragma unroll
            for (int o = 0; o < OCG; o++)
                ub[o][cl / 3] = maj3s2(vb[o][0], vb[o][1], vb[o][2], NEG2);
        }
    }

    u64 tp[OCG];
    #pragma unroll
    for (int o = 0; o < OCG; o++)
        tp[o] = maj3s2(ub[o][0], ub[o][1], ub[o][2], NEG2);

    // ---- exchange packed partials via smem aliased over xs
    __syncthreads();
    u64* part = (u64*)xs;   // 9*128*8 = 9216 B < sizeof(xs)
    #pragma unroll
    for (int o = 0; o < OCG; o++)
        part[(cg * OCG + o) * NPAIR + pp] = tp[o];
    __syncthreads();

    // ---- thread (pp, cg) finalizes oc = cg for its pixel pair
    u64 t0 = part[(0 * OCG + cg) * NPAIR + pp];
    u64 t1 = part[(1 * OCG + cg) * NPAIR + pp];
    u64 t2 = part[(2 * OCG + cg) * NPAIR + pp];
    u64 rr = maj3s2(t0, t1, t2, NEG2);
    u64 y2 = ffma2(pk2(2.0f, 2.0f), rr, pk2(-1.0f, -1.0f));
    float ylo, yhi;
    upk2(y2, ylo, yhi);

    int hg = h0 + hl;
    float2* op = (float2*)&out[(((size_t)n * NOC + (oc0 + cg)) * HH + hg) * WW + 2 * wc2];
    *op = make_float2(ylo, yhi);
}

extern "C" void kernel_launch(void* const* d_in, const int* in_sizes, int n_in,
                              void* d_out, int out_size) {
    const float* x = (const float*)d_in[0];     // (8,27,32,32) fp32
    const float* w = (const float*)d_in[1];     // (27,27,3,3) fp32
    float* out = (float*)d_out;                 // (8,27,32,32) fp32

    dim3 grid(8 * 4 * (NOC / OCG));   // 288 blocks x 384 threads
    sconv_kernel<<<grid, NTHR>>>(x, w, out);
}

// round 8
// speedup vs baseline: 1.2195x; 1.2195x over previous
#include <cuda_runtime.h>

// SConv2d majority-gate conv, s-domain math, packed f32x2 (2 px/thread).
// R7: dual-alignment x tile (normal + 1-col-shifted shadow copy) so all three
//     window pairs per row are direct aligned LDS.64 — removes all pk2 MOVs.

#define C_IN 27
#define NOC 27
#define HH 32
#define WW 32
#define TILE_H 8
#define SM_ROWS (TILE_H + 2)       // 10
#define SM_W 36
#define SM_CH (SM_ROWS * SM_W)     // 360
#define OCG 3
#define WP2 10                     // packed-weight stride per (oc,c) in u64
#define NPAIR 128                  // pixel pairs per tile
#define NTHR (NPAIR * 3)           // 384

// dynamic smem layout (float units):
//   xsA [C_IN*SM_CH]   x[m] at col m+2  (cols 1..34 used; halos at 1,34)
//   xsB [C_IN*SM_CH]   x[m] at col m+3  (cols 2..35 used; halos at 2,35)
//   wsm [OCG*C_IN*WP2] u64 packed {w/2,w/2}
#define XSB_OFF (C_IN * SM_CH)
#define WSM_OFF (2 * C_IN * SM_CH)                    // float index; 16B aligned
#define SMEM_BYTES ((2 * C_IN * SM_CH) * 4 + OCG * C_IN * WP2 * 8)

typedef unsigned long long u64;

__device__ __forceinline__ u64 pk2(float lo, float hi) {
    u64 r; asm("mov.b64 %0,{%1,%2};" : "=l"(r) : "f"(lo), "f"(hi)); return r;
}
__device__ __forceinline__ void upk2(u64 v, float& lo, float& hi) {
    asm("mov.b64 {%0,%1},%2;" : "=f"(lo), "=f"(hi) : "l"(v));
}
__device__ __forceinline__ u64 ffma2(u64 a, u64 b, u64 c) {
    u64 d; asm("fma.rn.f32x2 %0,%1,%2,%3;" : "=l"(d) : "l"(a), "l"(b), "l"(c)); return d;
}
__device__ __forceinline__ u64 fmul2(u64 a, u64 b) {
    u64 d; asm("mul.rn.f32x2 %0,%1,%2;" : "=l"(d) : "l"(a), "l"(b)); return d;
}
__device__ __forceinline__ u64 fadd2(u64 a, u64 b) {
    u64 d; asm("add.rn.f32x2 %0,%1,%2;" : "=l"(d) : "l"(a), "l"(b)); return d;
}
__device__ __forceinline__ u64 maj3s2(u64 a, u64 b, u64 c, u64 NEG2) {
    u64 p = fmul2(a, b);
    u64 t = fadd2(a, b);
    u64 q = ffma2(NEG2, p, t);     // a+b-2ab
    return ffma2(q, c, p);         // ab + (a+b-2ab)c
}

__global__ __launch_bounds__(NTHR, 2) void sconv_kernel(const float* __restrict__ x,
                                                        const float* __restrict__ w,
                                                        float* __restrict__ out) {
    extern __shared__ __align__(16) float smem[];
    float* xsA = smem;
    float* xsB = smem + XSB_OFF;
    u64*   wsm = (u64*)(smem + WSM_OFF);

    int b = blockIdx.x;
    int ocg  = b % (NOC / OCG);        // 0..8
    int tile = (b / (NOC / OCG)) & 3;  // 0..3
    int n    = b / (4 * (NOC / OCG));  // 0..7
    int h0 = tile * TILE_H;
    int oc0 = ocg * OCG;

    int tid = threadIdx.x;

    // ---- stage weights packed {w/2, w/2}
    for (int idx = tid; idx < OCG * C_IN * 9; idx += NTHR) {
        int ocl = idx / (C_IN * 9);
        int rem = idx - ocl * (C_IN * 9);
        int c = rem / 9;
        int k = rem - c * 9;
        float v = 0.5f * w[(oc0 + ocl) * (C_IN * 9) + rem];
        wsm[(ocl * C_IN + c) * WP2 + k] = pk2(v, v);
    }

    // ---- stage x tile interior into BOTH copies; halos = -1
    const float* xn = x + (size_t)n * C_IN * HH * WW;
    for (int idx = tid; idx < C_IN * SM_ROWS * 32; idx += NTHR) {
        int rowid = idx >> 5;
        int col   = idx & 31;
        int c = rowid / SM_ROWS;
        int r = rowid - c * SM_ROWS;
        int gh = h0 + r - 1;
        float v = -1.0f;
        if ((unsigned)gh < HH)
            v = xn[(c << 10) + (gh << 5) + col];
        int base = c * SM_CH + r * SM_W;
        xsA[base + col + 2] = v;
        xsB[base + col + 3] = v;
    }
    for (int idx = tid; idx < C_IN * SM_ROWS; idx += NTHR) {
        int base = idx * SM_W;
        xsA[base + 1]  = -1.0f;    // x[-1]
        xsA[base + 34] = -1.0f;    // x[32]
        xsB[base + 2]  = -1.0f;    // x[-1]
        xsB[base + 35] = -1.0f;    // x[32]
    }
    __syncthreads();

    int pp  = tid & (NPAIR - 1);       // pair index 0..127
    int cg  = tid >> 7;                // channel group 0..2
    int wc2 = pp & 15;                 // pair column (cols 2*wc2, 2*wc2+1)
    int hl  = pp >> 4;                 // local row 0..7
    int wpx = 2 * wc2;

    const u64 HALF2 = pk2(0.5f, 0.5f);
    const u64 NEG2  = pk2(-2.0f, -2.0f);

    int rbase = hl * SM_W + wpx;       // + c*SM_CH + kh*SM_W gives row start
    int c0 = 9 * cg;

    u64 vb[OCG][3], ub[OCG][3];

    #pragma unroll
    for (int cl = 0; cl < 9; cl++) {
        int c = c0 + cl;
        // 9 window pairs, all direct aligned LDS.64
        u64 xp[9];
        #pragma unroll
        for (int kh = 0; kh < 3; kh++) {
            int ro = c * SM_CH + kh * SM_W + rbase;
            xp[kh * 3 + 0] = *(const u64*)&xsB[ro + 2];   // {x[w-1], x[w]}
            xp[kh * 3 + 1] = *(const u64*)&xsA[ro + 2];   // {x[w],   x[w+1]}
            xp[kh * 3 + 2] = *(const u64*)&xsB[ro + 4];   // {x[w+1], x[w+2]}
        }
        #pragma unroll
        for (int o = 0; o < OCG; o++) {
            const u64* wb_ = &wsm[(o * C_IN + c) * WP2];
            ulonglong2 q0 = ((const ulonglong2*)wb_)[0];
            ulonglong2 q1 = ((const ulonglong2*)wb_)[1];
            ulonglong2 q2 = ((const ulonglong2*)wb_)[2];
            ulonglong2 q3 = ((const ulonglong2*)wb_)[3];
            u64 w8 = wb_[8];
            u64 wk[9] = {q0.x, q0.y, q1.x, q1.y, q2.x, q2.y, q3.x, q3.y, w8};
            u64 rkh[3];
            #pragma unroll
            for (int kh = 0; kh < 3; kh++) {
                u64 s0 = ffma2(xp[kh * 3 + 0], wk[kh * 3 + 0], HALF2);
                u64 s1 = ffma2(xp[kh * 3 + 1], wk[kh * 3 + 1], HALF2);
                u64 s2 = ffma2(xp[kh * 3 + 2], wk[kh * 3 + 2], HALF2);
                rkh[kh] = maj3s2(s0, s1, s2, NEG2);
            }
            vb[o][cl % 3] = maj3s2(rkh[0], rkh[1], rkh[2], NEG2);
        }
        if (cl % 3 == 2) {
            #pragma unroll
            for (int o = 0; o < OCG; o++)
                ub[o][cl / 3] = maj3s2(vb[o][0], vb[o][1], vb[o][2], NEG2);
        }
    }

    u64 tp[OCG];
    #pragma unroll
    for (int o = 0; o < OCG; o++)
        tp[o] = maj3s2(ub[o][0], ub[o][1], ub[o][2], NEG2);

    // ---- exchange packed partials via smem aliased over xsA
    __syncthreads();
    u64* part = (u64*)smem;   // 9*128*8 = 9216 B, fits in xsA region
    #pragma unroll
    for (int o = 0; o < OCG; o++)
        part[(cg * OCG + o) * NPAIR + pp] = tp[o];
    __syncthreads();

    // ---- thread (pp, cg) finalizes oc = cg for its pixel pair
    u64 t0 = part[(0 * OCG + cg) * NPAIR + pp];
    u64 t1 = part[(1 * OCG + cg) * NPAIR + pp];
    u64 t2 = part[(2 * OCG + cg) * NPAIR + pp];
    u64 rr = maj3s2(t0, t1, t2, NEG2);
    u64 y2 = ffma2(pk2(2.0f, 2.0f), rr, pk2(-1.0f, -1.0f));
    float ylo, yhi;
    upk2(y2, ylo, yhi);

    int hg = h0 + hl;
    float2* op = (float2*)&out[(((size_t)n * NOC + (oc0 + cg)) * HH + hg) * WW + wpx];
    *op = make_float2(ylo, yhi);
}

extern "C" void kernel_launch(void* const* d_in, const int* in_sizes, int n_in,
                              void* d_out, int out_size) {
    const float* x = (const float*)d_in[0];     // (8,27,32,32) fp32
    const float* w = (const float*)d_in[1];     // (27,27,3,3) fp32
    float* out = (float*)d_out;                 // (8,27,32,32) fp32

    static int smem_set = 0;
    if (!smem_set) {
        cudaFuncSetAttribute(sconv_kernel,
                             cudaFuncAttributeMaxDynamicSharedMemorySize,
                             SMEM_BYTES);
        smem_set = 1;
    }

    dim3 grid(8 * 4 * (NOC / OCG));   // 288 blocks x 384 threads
    sconv_kernel<<<grid, NTHR, SMEM_BYTES>>>(x, w, out);
}